// round 15
// baseline (speedup 1.0000x reference)
#include <cuda_runtime.h>
#include <cstdint>

#define U_N   100000
#define I_N   50000
#define R_N   5
#define E_N   100000
#define K_N   4
#define D_N   16
#define RD_N  64
#define OUT_N 64
#define KF_N  2
#define PS_EDGES 64

// ---------------- device scratch ----------------
__device__ float g_norm_u[U_N];
__device__ float g_norm_i[I_N];
__device__ float g_ead[R_N * E_N];
__device__ float g_eadp[R_N * E_N];             // prototype-softmax part of ead
__device__ float g_m[(size_t)R_N * E_N * 32];   // per edge: [0..15]=fwd, [16..31]=rev
__device__ float g_ufeat[U_N * D_N];
__device__ float g_ifeat[I_N * D_N];
__device__ float g_P_u[(size_t)R_N * U_N * D_N];
__device__ float g_P_i[(size_t)R_N * I_N * D_N];

// ---------------- helpers ----------------
__device__ __forceinline__ float red16(float v) {
    v += __shfl_xor_sync(0xffffffffu, v, 1);
    v += __shfl_xor_sync(0xffffffffu, v, 2);
    v += __shfl_xor_sync(0xffffffffu, v, 4);
    v += __shfl_xor_sync(0xffffffffu, v, 8);
    return v;
}
__device__ __forceinline__ void red_v4(float* addr, float4 v) {
    asm volatile("red.global.add.v4.f32 [%0], {%1, %2, %3, %4};"
                 :: "l"(addr), "f"(v.x), "f"(v.y), "f"(v.z), "f"(v.w)
                 : "memory");
}
__device__ __forceinline__ unsigned long long dup2(float v) {
    unsigned long long d;
    asm("mov.b64 %0, {%1, %1};" : "=l"(d) : "f"(v));
    return d;
}
__device__ __forceinline__ unsigned long long pack2(float lo, float hi) {
    unsigned long long d;
    asm("mov.b64 %0, {%1, %2};" : "=l"(d) : "f"(lo), "f"(hi));
    return d;
}
__device__ __forceinline__ unsigned long long fma2(unsigned long long a,
                                                   unsigned long long b,
                                                   unsigned long long c) {
    unsigned long long d;
    asm("fma.rn.f32x2 %0, %1, %2, %3;" : "=l"(d) : "l"(a), "l"(b), "l"(c));
    return d;
}
__device__ __forceinline__ void unpack2(unsigned long long v, float& lo, float& hi) {
    asm("mov.b64 {%0, %1}, %2;" : "=f"(lo), "=f"(hi) : "l"(v));
}

// ---------------- kernel A: node projection + accumulator zeroing ----------------
__global__ __launch_bounds__(256) void precompute_kernel(
    const float* __restrict__ user_h, const float* __restrict__ item_h,
    const float* __restrict__ node_w_fwd, const float* __restrict__ node_w_rev)
{
    __shared__ float sw[256];
    const int r = blockIdx.y;
    const bool isU = (blockIdx.z == 0);
    const float* W = isU ? node_w_fwd : node_w_rev;
    if (threadIdx.x < 256) sw[threadIdx.x] = W[r * 256 + threadIdx.x];
    __syncthreads();

    const int N = isU ? U_N : I_N;
    const int n = blockIdx.x * 256 + threadIdx.x;
    if (n >= N) return;

    if (r == 0) {
        float4 z = {0.f, 0.f, 0.f, 0.f};
        if (isU) {
            g_norm_u[n] = 0.f;
            float4* f = (float4*)(g_ufeat + n * 16);
            f[0] = z; f[1] = z; f[2] = z; f[3] = z;
        } else {
            g_norm_i[n] = 0.f;
            float4* f = (float4*)(g_ifeat + n * 16);
            f[0] = z; f[1] = z; f[2] = z; f[3] = z;
        }
    }

    const float* h = (isU ? user_h : item_h) + ((size_t)r * N + n) * 16;
    float xs[16];
    const float4* h4 = (const float4*)h;
    float4 x0 = h4[0], x1 = h4[1], x2 = h4[2], x3 = h4[3];
    xs[0]=x0.x; xs[1]=x0.y; xs[2]=x0.z; xs[3]=x0.w;
    xs[4]=x1.x; xs[5]=x1.y; xs[6]=x1.z; xs[7]=x1.w;
    xs[8]=x2.x; xs[9]=x2.y; xs[10]=x2.z; xs[11]=x2.w;
    xs[12]=x3.x; xs[13]=x3.y; xs[14]=x3.z; xs[15]=x3.w;

    float4 a0 = {0,0,0,0}, a1 = {0,0,0,0}, a2 = {0,0,0,0}, a3 = {0,0,0,0};
    const float4* sw4 = (const float4*)sw;
#pragma unroll
    for (int j = 0; j < 16; j++) {
        float xv = xs[j];
        float4 w0 = sw4[j*4+0], w1 = sw4[j*4+1], w2 = sw4[j*4+2], w3 = sw4[j*4+3];
        a0.x = fmaf(xv, w0.x, a0.x); a0.y = fmaf(xv, w0.y, a0.y);
        a0.z = fmaf(xv, w0.z, a0.z); a0.w = fmaf(xv, w0.w, a0.w);
        a1.x = fmaf(xv, w1.x, a1.x); a1.y = fmaf(xv, w1.y, a1.y);
        a1.z = fmaf(xv, w1.z, a1.z); a1.w = fmaf(xv, w1.w, a1.w);
        a2.x = fmaf(xv, w2.x, a2.x); a2.y = fmaf(xv, w2.y, a2.y);
        a2.z = fmaf(xv, w2.z, a2.z); a2.w = fmaf(xv, w2.w, a2.w);
        a3.x = fmaf(xv, w3.x, a3.x); a3.y = fmaf(xv, w3.y, a3.y);
        a3.z = fmaf(xv, w3.z, a3.z); a3.w = fmaf(xv, w3.w, a3.w);
    }
    float4* P = (float4*)((isU ? g_P_u : g_P_i) + ((size_t)r * N + n) * 16);
    P[0] = a0; P[1] = a1; P[2] = a2; P[3] = a3;
}

// ---------------- review kernel: proto dots (eadp) + projection GEMM (g_m) ----------------
// Single pass over review_feat. Block = 64 edges.
__global__ __launch_bounds__(256) void review_kernel(
    const float* __restrict__ review_feat, const float* __restrict__ prototypes,
    const float* __restrict__ review_w_fwd, const float* __restrict__ review_w_rev)
{
    __shared__ float      smProto[256];
    __shared__ float      smW[64 * 36];
    __shared__ ulonglong2 smrf[32 * 33];

    const int r = blockIdx.y;
    const int tid = threadIdx.x;
    const int lane = tid & 31;
    const int warp = tid >> 5;
    const int e0 = blockIdx.x * PS_EDGES;
    const unsigned FULL = 0xffffffffu;

    if (tid < 256) smProto[tid] = prototypes[tid];
    for (int i = tid; i < 2048; i += 256) {
        int o = i & 31, j = i >> 5;
        float w = (o < 16) ? review_w_fwd[r * 1024 + j * 16 + o]
                           : review_w_rev[r * 1024 + j * 16 + (o - 16)];
        smW[j * 36 + o] = w;
    }
    __syncthreads();

    // ---- dots phase: warp handles 8 edges sequentially ----
    {
        const float4* pr4 = (const float4*)smProto;
        const float4 pa = pr4[lane * 2];
        const float4 pb = pr4[lane * 2 + 1];
        const bool is_k = (lane >= 16 && lane < 24);   // lane's chunk is rf_k slice
#pragma unroll
        for (int ee = 0; ee < 8; ee++) {
            int e = e0 + warp * 8 + ee;
            if (e >= E_N) break;
            const size_t idx = (size_t)r * E_N + e;
            const float4* rf4 = (const float4*)(review_feat + idx * 256);
            float4 ra, rb;
            if (is_k) { ra = rf4[lane * 2]; rb = rf4[lane * 2 + 1]; }       // keep in L2
            else      { ra = __ldcs(rf4 + lane * 2); rb = __ldcs(rf4 + lane * 2 + 1); }
            float ad = ra.x * pa.x + ra.y * pa.y + ra.z * pa.z + ra.w * pa.w
                     + rb.x * pb.x + rb.y * pb.y + rb.z * pb.z + rb.w * pb.w;
            ad += __shfl_xor_sync(FULL, ad, 1);
            ad += __shfl_xor_sync(FULL, ad, 2);
            ad += __shfl_xor_sync(FULL, ad, 4);
            float eab = __expf(2.0f * ad);
            float Sad = eab;
            Sad += __shfl_xor_sync(FULL, Sad, 8);
            Sad += __shfl_xor_sync(FULL, Sad, 16);
            float e2 = __shfl_sync(FULL, eab, 16);
            if (lane == 0) g_eadp[idx] = e2 / Sad;
        }
    }

    // ---- GEMM staging: rf_k re-read (L2-hot), zip in registers ----
    for (int i = tid; i < 512; i += 256) {
        int p = i >> 4, q = i & 15;
        int ee = e0 + 2 * p;
        float4 v0 = {0,0,0,0}, v1 = {0,0,0,0};
        if (ee < E_N)
            v0 = *((const float4*)(review_feat + ((size_t)r * E_N + ee) * 256 + 128) + q);
        if (ee + 1 < E_N)
            v1 = *((const float4*)(review_feat + ((size_t)r * E_N + ee + 1) * 256 + 128) + q);
        ulonglong2 za, zb;
        za.x = pack2(v0.x, v1.x);
        za.y = pack2(v0.y, v1.y);
        zb.x = pack2(v0.z, v1.z);
        zb.y = pack2(v0.w, v1.w);
        smrf[p * 33 + q * 2]     = za;
        smrf[p * 33 + q * 2 + 1] = zb;
    }
    __syncthreads();

    // ---- GEMM: warp owns 4 pairs x 32 outs; lane = (pair_local, o4) ----
    const int p_local = lane >> 3;
    const int o4 = lane & 7;
    const int pair = warp * 4 + p_local;
    unsigned long long acc2[4] = {0ull, 0ull, 0ull, 0ull};
    const ulonglong2* rfp = smrf + pair * 33;
    const float* wp = smW + o4 * 4;
#pragma unroll
    for (int jq = 0; jq < 16; jq++) {
        ulonglong2 rva = rfp[jq * 2];
        ulonglong2 rvb = rfp[jq * 2 + 1];
        float4 w0 = *(const float4*)(wp + (4*jq+0) * 36);
        float4 w1 = *(const float4*)(wp + (4*jq+1) * 36);
        float4 w2 = *(const float4*)(wp + (4*jq+2) * 36);
        float4 w3 = *(const float4*)(wp + (4*jq+3) * 36);
        acc2[0] = fma2(rva.x, dup2(w0.x), acc2[0]);
        acc2[1] = fma2(rva.x, dup2(w0.y), acc2[1]);
        acc2[2] = fma2(rva.x, dup2(w0.z), acc2[2]);
        acc2[3] = fma2(rva.x, dup2(w0.w), acc2[3]);
        acc2[0] = fma2(rva.y, dup2(w1.x), acc2[0]);
        acc2[1] = fma2(rva.y, dup2(w1.y), acc2[1]);
        acc2[2] = fma2(rva.y, dup2(w1.z), acc2[2]);
        acc2[3] = fma2(rva.y, dup2(w1.w), acc2[3]);
        acc2[0] = fma2(rvb.x, dup2(w2.x), acc2[0]);
        acc2[1] = fma2(rvb.x, dup2(w2.y), acc2[1]);
        acc2[2] = fma2(rvb.x, dup2(w2.z), acc2[2]);
        acc2[3] = fma2(rvb.x, dup2(w2.w), acc2[3]);
        acc2[0] = fma2(rvb.y, dup2(w3.x), acc2[0]);
        acc2[1] = fma2(rvb.y, dup2(w3.y), acc2[1]);
        acc2[2] = fma2(rvb.y, dup2(w3.z), acc2[2]);
        acc2[3] = fma2(rvb.y, dup2(w3.w), acc2[3]);
    }

    float4 lo4, hi4;
    unpack2(acc2[0], lo4.x, hi4.x);
    unpack2(acc2[1], lo4.y, hi4.y);
    unpack2(acc2[2], lo4.z, hi4.z);
    unpack2(acc2[3], lo4.w, hi4.w);
    int e_even = e0 + pair * 2;
    if (e_even < E_N)
        *(float4*)(g_m + ((size_t)r * E_N + e_even) * 32 + o4 * 4) = lo4;
    if (e_even + 1 < E_N)
        *(float4*)(g_m + ((size_t)r * E_N + e_even + 1) * 32 + o4 * 4) = hi4;
}

// ---------------- phase1p: ead from gathers + eadp; no review traffic ----------------
__global__ __launch_bounds__(256) void phase1p_kernel(
    const float* __restrict__ user_h,     const float* __restrict__ item_h,
    const float* __restrict__ user_hsum,  const float* __restrict__ item_hsum,
    const float* __restrict__ eta,
    const int*   __restrict__ rows,       const int*   __restrict__ cols)
{
    const int lane = threadIdx.x & 31;
    const int warp = threadIdx.x >> 5;
    const int e = blockIdx.x * 8 + warp;
    if (e >= E_N) return;
    const int r = blockIdx.y;

    const size_t idx = (size_t)r * E_N + e;
    const int row = rows[idx];
    const int col = cols[idx];
    const unsigned FULL = 0xffffffffu;

    const int dh = lane & 15;
    float hval;
    if (lane < 16) hval = __ldg(user_h + ((size_t)r * U_N + row) * 16 + dh);
    else           hval = __ldg(item_h + ((size_t)r * I_N + col) * 16 + dh);

    const float* uh = user_hsum + ((size_t)r * U_N + row) * 64;
    const float* ih = item_hsum + ((size_t)r * I_N + col) * 64;
    float4 hs;
    if (lane < 16) hs = *(const float4*)(uh + 4 * lane);
    else           hs = *(const float4*)(ih + 4 * (lane - 16));

    const float etav = eta[idx];
    const float eadp = g_eadp[idx];

    float othv = __shfl_xor_sync(FULL, hval, 16);
    float dot = red16(hval * othv);
    float ss = red16(hval * hval);
    float oss = __shfl_xor_sync(FULL, ss, 16);
    float sim_k = 2.0f * dot * rsqrtf(ss * oss);

    float4 o4;
    o4.x = __shfl_xor_sync(FULL, hs.x, 16);
    o4.y = __shfl_xor_sync(FULL, hs.y, 16);
    o4.z = __shfl_xor_sync(FULL, hs.z, 16);
    o4.w = __shfl_xor_sync(FULL, hs.w, 16);
    float p = hs.x * o4.x + hs.y * o4.y + hs.z * o4.z + hs.w * o4.w;
    p += __shfl_xor_sync(FULL, p, 1);
    p += __shfl_xor_sync(FULL, p, 2);
    float ek = __expf(2.0f * p);
    float Ssim = ek;
    Ssim += __shfl_xor_sync(FULL, Ssim, 4);
    Ssim += __shfl_xor_sync(FULL, Ssim, 8);
    float exp_sim = __expf(sim_k) / Ssim;

    float g = 1.0f / (1.0f + __expf(-etav));
    float ead = g * eadp + (1.0f - g) * exp_sim;

    if (lane == 0) {
        g_ead[idx] = ead;
        atomicAdd(&g_norm_u[row], ead);
        atomicAdd(&g_norm_i[col], ead);
    }
}

// ---------------- phase2: weight + gather P + v4 RED scatter ----------------
__global__ __launch_bounds__(256) void phase2_kernel(
    const int* __restrict__ rows, const int* __restrict__ cols,
    float* __restrict__ int_dist_out)
{
    const int t = blockIdx.x * 256 + threadIdx.x;
    const int e = t >> 3;
    const int q = t & 7;
    if (e >= E_N) return;
    const int r = blockIdx.y;
    const size_t idx = (size_t)r * E_N + e;

    const int row = rows[idx];
    const int col = cols[idx];
    const float ead = g_ead[idx];
    const float w = ead * rsqrtf(g_norm_u[row] * g_norm_i[col]);
    if (q == 0) int_dist_out[idx] = w;

    float4 m4, p4;
    float* dest;
    if (q < 4) {
        m4 = *(const float4*)(g_m + idx * 32 + q * 4);
        p4 = *(const float4*)(g_P_u + ((size_t)r * U_N + row) * 16 + q * 4);
        dest = g_ifeat + col * 16 + q * 4;
    } else {
        const int qq = q - 4;
        m4 = *(const float4*)(g_m + idx * 32 + 16 + qq * 4);
        p4 = *(const float4*)(g_P_i + ((size_t)r * I_N + col) * 16 + qq * 4);
        dest = g_ufeat + row * 16 + qq * 4;
    }
    float4 mv;
    mv.x = (m4.x + p4.x) * w;
    mv.y = (m4.y + p4.y) * w;
    mv.z = (m4.z + p4.z) * w;
    mv.w = (m4.w + p4.w) * w;
    red_v4(dest, mv);
}

// ---------------- kernel 3: leaky + FC (R13 version) ----------------
#define NB_U ((U_N + 63) / 64)
#define NB_I ((I_N + 63) / 64)
__global__ __launch_bounds__(256) void fc_kernel(
    const float* __restrict__ ufc_w, const float* __restrict__ ufc_b,
    const float* __restrict__ ifc_w, const float* __restrict__ ifc_b,
    float* __restrict__ out)
{
    __shared__ float smx[64 * 20];
    const int tid = threadIdx.x;
    const bool isU = (blockIdx.x < NB_U);
    const int nb = (isU ? blockIdx.x : (blockIdx.x - NB_U)) * 64;
    const int N = isU ? U_N : I_N;
    const float* feat = isU ? g_ufeat : g_ifeat;
    const float* W = isU ? ufc_w : ifc_w;
    const float* B = isU ? ufc_b : ifc_b;
    float* outp = out + (isU ? 0 : (size_t)U_N * 64);

    for (int i = tid; i < 1024; i += 256) {
        int n = i >> 4, j = i & 15;
        int ng = nb + n;
        float x = (ng < N) ? feat[ng * 16 + j] : 0.f;
        x = (x >= 0.f) ? x : 0.1f * x;
        smx[n * 20 + j] = x;
    }
    __syncthreads();

    const int o = tid & 63;
    const int g = tid >> 6;
    float wr[16];
#pragma unroll
    for (int j = 0; j < 16; j++) wr[j] = W[j * 64 + o];
    const float b = B[o];

#pragma unroll
    for (int i = 0; i < 16; i++) {
        int n = g + i * 4;
        int ng = nb + n;
        if (ng < N) {
            float acc = b;
            const float4* xr = (const float4*)(smx + n * 20);
#pragma unroll
            for (int j4 = 0; j4 < 4; j4++) {
                float4 xq = xr[j4];
                acc = fmaf(xq.x, wr[j4*4+0], acc);
                acc = fmaf(xq.y, wr[j4*4+1], acc);
                acc = fmaf(xq.z, wr[j4*4+2], acc);
                acc = fmaf(xq.w, wr[j4*4+3], acc);
            }
            outp[(size_t)ng * 64 + o] = acc;
        }
    }
}

// ---------------- launch (single stream, no forks) ----------------
extern "C" void kernel_launch(void* const* d_in, const int* in_sizes, int n_in,
                              void* d_out, int out_size)
{
    const float* user_h       = (const float*)d_in[0];
    const float* item_h       = (const float*)d_in[1];
    const float* user_hsum    = (const float*)d_in[2];
    const float* item_hsum    = (const float*)d_in[3];
    const float* review_feat  = (const float*)d_in[4];
    const float* prototypes   = (const float*)d_in[5];
    const float* eta          = (const float*)d_in[6];
    const float* node_w_fwd   = (const float*)d_in[7];
    const float* node_w_rev   = (const float*)d_in[8];
    const float* review_w_fwd = (const float*)d_in[9];
    const float* review_w_rev = (const float*)d_in[10];
    const float* ufc_w        = (const float*)d_in[11];
    const float* ufc_b        = (const float*)d_in[12];
    const float* ifc_w        = (const float*)d_in[13];
    const float* ifc_b        = (const float*)d_in[14];
    const int*   rows         = (const int*)d_in[15];
    const int*   cols         = (const int*)d_in[16];
    float* out = (float*)d_out;

    dim3 pgrid((U_N + 255) / 256, R_N, 2);
    precompute_kernel<<<pgrid, 256>>>(user_h, item_h, node_w_fwd, node_w_rev);

    dim3 rgrid((E_N + PS_EDGES - 1) / PS_EDGES, R_N);
    review_kernel<<<rgrid, 256>>>(review_feat, prototypes,
                                  review_w_fwd, review_w_rev);

    dim3 egrid(E_N / 8, R_N);
    phase1p_kernel<<<egrid, 256>>>(user_h, item_h, user_hsum, item_hsum,
                                   eta, rows, cols);

    dim3 p2grid((E_N * 8 + 255) / 256, R_N);
    phase2_kernel<<<p2grid, 256>>>(rows, cols, out + (size_t)(U_N + I_N) * OUT_N);

    fc_kernel<<<NB_U + NB_I, 256>>>(ufc_w, ufc_b, ifc_w, ifc_b, out);
}

// round 16
// speedup vs baseline: 1.1210x; 1.1210x over previous
#include <cuda_runtime.h>
#include <cstdint>

#define U_N   100000
#define I_N   50000
#define R_N   5
#define E_N   100000
#define K_N   4
#define D_N   16
#define RD_N  64
#define OUT_N 64
#define KF_N  2
#define PS_EDGES 64

// ---------------- device scratch ----------------
__device__ float g_norm_u[U_N];
__device__ float g_norm_i[I_N];
__device__ float g_ead[R_N * E_N];
__device__ float g_ufeat[U_N * D_N];
__device__ float g_ifeat[I_N * D_N];
__device__ float g_P_u[(size_t)R_N * U_N * D_N];
__device__ float g_P_i[(size_t)R_N * I_N * D_N];

// ---------------- helpers ----------------
__device__ __forceinline__ float red16(float v) {
    v += __shfl_xor_sync(0xffffffffu, v, 1);
    v += __shfl_xor_sync(0xffffffffu, v, 2);
    v += __shfl_xor_sync(0xffffffffu, v, 4);
    v += __shfl_xor_sync(0xffffffffu, v, 8);
    return v;
}
__device__ __forceinline__ void red_v4(float* addr, float4 v) {
    asm volatile("red.global.add.v4.f32 [%0], {%1, %2, %3, %4};"
                 :: "l"(addr), "f"(v.x), "f"(v.y), "f"(v.z), "f"(v.w)
                 : "memory");
}
__device__ __forceinline__ unsigned long long dup2(float v) {
    unsigned long long d;
    asm("mov.b64 %0, {%1, %1};" : "=l"(d) : "f"(v));
    return d;
}
__device__ __forceinline__ unsigned long long pack2(float lo, float hi) {
    unsigned long long d;
    asm("mov.b64 %0, {%1, %2};" : "=l"(d) : "f"(lo), "f"(hi));
    return d;
}
__device__ __forceinline__ unsigned long long fma2(unsigned long long a,
                                                   unsigned long long b,
                                                   unsigned long long c) {
    unsigned long long d;
    asm("fma.rn.f32x2 %0, %1, %2, %3;" : "=l"(d) : "l"(a), "l"(b), "l"(c));
    return d;
}
__device__ __forceinline__ void unpack2(unsigned long long v, float& lo, float& hi) {
    asm("mov.b64 {%0, %1}, %2;" : "=f"(lo), "=f"(hi) : "l"(v));
}

// ---------------- kernel A: node projection + accumulator zeroing ----------------
__global__ __launch_bounds__(256) void precompute_kernel(
    const float* __restrict__ user_h, const float* __restrict__ item_h,
    const float* __restrict__ node_w_fwd, const float* __restrict__ node_w_rev)
{
    __shared__ float sw[256];
    const int r = blockIdx.y;
    const bool isU = (blockIdx.z == 0);
    const float* W = isU ? node_w_fwd : node_w_rev;
    if (threadIdx.x < 256) sw[threadIdx.x] = W[r * 256 + threadIdx.x];
    __syncthreads();

    const int N = isU ? U_N : I_N;
    const int n = blockIdx.x * 256 + threadIdx.x;
    if (n >= N) return;

    if (r == 0) {
        float4 z = {0.f, 0.f, 0.f, 0.f};
        if (isU) {
            g_norm_u[n] = 0.f;
            float4* f = (float4*)(g_ufeat + n * 16);
            f[0] = z; f[1] = z; f[2] = z; f[3] = z;
        } else {
            g_norm_i[n] = 0.f;
            float4* f = (float4*)(g_ifeat + n * 16);
            f[0] = z; f[1] = z; f[2] = z; f[3] = z;
        }
    }

    const float* h = (isU ? user_h : item_h) + ((size_t)r * N + n) * 16;
    float xs[16];
    const float4* h4 = (const float4*)h;
    float4 x0 = h4[0], x1 = h4[1], x2 = h4[2], x3 = h4[3];
    xs[0]=x0.x; xs[1]=x0.y; xs[2]=x0.z; xs[3]=x0.w;
    xs[4]=x1.x; xs[5]=x1.y; xs[6]=x1.z; xs[7]=x1.w;
    xs[8]=x2.x; xs[9]=x2.y; xs[10]=x2.z; xs[11]=x2.w;
    xs[12]=x3.x; xs[13]=x3.y; xs[14]=x3.z; xs[15]=x3.w;

    float4 a0 = {0,0,0,0}, a1 = {0,0,0,0}, a2 = {0,0,0,0}, a3 = {0,0,0,0};
    const float4* sw4 = (const float4*)sw;
#pragma unroll
    for (int j = 0; j < 16; j++) {
        float xv = xs[j];
        float4 w0 = sw4[j*4+0], w1 = sw4[j*4+1], w2 = sw4[j*4+2], w3 = sw4[j*4+3];
        a0.x = fmaf(xv, w0.x, a0.x); a0.y = fmaf(xv, w0.y, a0.y);
        a0.z = fmaf(xv, w0.z, a0.z); a0.w = fmaf(xv, w0.w, a0.w);
        a1.x = fmaf(xv, w1.x, a1.x); a1.y = fmaf(xv, w1.y, a1.y);
        a1.z = fmaf(xv, w1.z, a1.z); a1.w = fmaf(xv, w1.w, a1.w);
        a2.x = fmaf(xv, w2.x, a2.x); a2.y = fmaf(xv, w2.y, a2.y);
        a2.z = fmaf(xv, w2.z, a2.z); a2.w = fmaf(xv, w2.w, a2.w);
        a3.x = fmaf(xv, w3.x, a3.x); a3.y = fmaf(xv, w3.y, a3.y);
        a3.z = fmaf(xv, w3.z, a3.z); a3.w = fmaf(xv, w3.w, a3.w);
    }
    float4* P = (float4*)((isU ? g_P_u : g_P_i) + ((size_t)r * N + n) * 16);
    P[0] = a0; P[1] = a1; P[2] = a2; P[3] = a3;
}

// ---------------- kernel 1: per-edge ead (R13 measured-best version) ----------------
__global__ __launch_bounds__(256) void phase1_kernel(
    const float* __restrict__ user_h,     const float* __restrict__ item_h,
    const float* __restrict__ user_hsum,  const float* __restrict__ item_hsum,
    const float* __restrict__ review_feat,
    const float* __restrict__ prototypes, const float* __restrict__ eta,
    const int*   __restrict__ rows,       const int*   __restrict__ cols)
{
    __shared__ float sm[256];
    const int r = blockIdx.y;
    if (threadIdx.x < 256) sm[threadIdx.x] = prototypes[threadIdx.x];
    __syncthreads();

    const int lane = threadIdx.x & 31;
    const int warp = threadIdx.x >> 5;
    const int e = blockIdx.x * 8 + warp;
    if (e >= E_N) return;

    const size_t idx = (size_t)r * E_N + e;
    const int row = rows[idx];
    const int col = cols[idx];
    const unsigned FULL = 0xffffffffu;

    const int dh = lane & 15;
    float hval;
    if (lane < 16) hval = __ldg(user_h + ((size_t)r * U_N + row) * 16 + dh);
    else           hval = __ldg(item_h + ((size_t)r * I_N + col) * 16 + dh);

    const float* uh = user_hsum + ((size_t)r * U_N + row) * 64;
    const float* ih = item_hsum + ((size_t)r * I_N + col) * 64;
    float4 hs;
    if (lane < 16) hs = *(const float4*)(uh + 4 * lane);
    else           hs = *(const float4*)(ih + 4 * (lane - 16));

    const float4* rf4 = (const float4*)(review_feat + idx * 256);
    float4 ra = __ldcs(rf4 + lane * 2);
    float4 rb = __ldcs(rf4 + lane * 2 + 1);

    const float etav = eta[idx];

    float othv = __shfl_xor_sync(FULL, hval, 16);
    float dot = red16(hval * othv);
    float ss = red16(hval * hval);
    float oss = __shfl_xor_sync(FULL, ss, 16);
    float sim_k = 2.0f * dot * rsqrtf(ss * oss);

    float4 o4;
    o4.x = __shfl_xor_sync(FULL, hs.x, 16);
    o4.y = __shfl_xor_sync(FULL, hs.y, 16);
    o4.z = __shfl_xor_sync(FULL, hs.z, 16);
    o4.w = __shfl_xor_sync(FULL, hs.w, 16);
    float p = hs.x * o4.x + hs.y * o4.y + hs.z * o4.z + hs.w * o4.w;
    p += __shfl_xor_sync(FULL, p, 1);
    p += __shfl_xor_sync(FULL, p, 2);
    float ek = __expf(2.0f * p);
    float Ssim = ek;
    Ssim += __shfl_xor_sync(FULL, Ssim, 4);
    Ssim += __shfl_xor_sync(FULL, Ssim, 8);
    float exp_sim = __expf(sim_k) / Ssim;

    const float4* pr4 = (const float4*)sm;
    float4 pa = pr4[lane * 2];
    float4 pb = pr4[lane * 2 + 1];
    float ad = ra.x * pa.x + ra.y * pa.y + ra.z * pa.z + ra.w * pa.w
             + rb.x * pb.x + rb.y * pb.y + rb.z * pb.z + rb.w * pb.w;
    ad += __shfl_xor_sync(FULL, ad, 1);
    ad += __shfl_xor_sync(FULL, ad, 2);
    ad += __shfl_xor_sync(FULL, ad, 4);
    float eab = __expf(2.0f * ad);
    float Sad = eab;
    Sad += __shfl_xor_sync(FULL, Sad, 8);
    Sad += __shfl_xor_sync(FULL, Sad, 16);
    float e2 = __shfl_sync(FULL, eab, 16);
    float ead = e2 / Sad;

    float g = 1.0f / (1.0f + __expf(-etav));
    ead = g * ead + (1.0f - g) * exp_sim;

    if (lane == 0) {
        g_ead[idx] = ead;
        atomicAdd(&g_norm_u[row], ead);
        atomicAdd(&g_norm_i[col], ead);
    }
}

// ---------------- fused kernel: zip-staging GEMM + w-stage + scatter (R13) ----------------
__global__ __launch_bounds__(256) void proj_scatter_kernel(
    const float* __restrict__ review_feat,
    const float* __restrict__ review_w_fwd, const float* __restrict__ review_w_rev,
    const int* __restrict__ rows, const int* __restrict__ cols,
    float* __restrict__ int_dist_out)
{
    __shared__ float      smW[64 * 36];
    __shared__ ulonglong2 smrf[32 * 33];
    __shared__ float      smw[PS_EDGES];
    __shared__ int2       smrc[PS_EDGES];
    float* smres = (float*)smrf;                    // overlay after GEMM

    const int r = blockIdx.y;
    const int tid = threadIdx.x;
    const int e0 = blockIdx.x * PS_EDGES;

    for (int i = tid; i < 2048; i += 256) {
        int o = i & 31, j = i >> 5;
        float w = (o < 16) ? review_w_fwd[r * 1024 + j * 16 + o]
                           : review_w_rev[r * 1024 + j * 16 + (o - 16)];
        smW[j * 36 + o] = w;
    }

    for (int i = tid; i < 512; i += 256) {
        int p = i >> 4, q = i & 15;
        int ee = e0 + 2 * p;
        float4 v0 = {0,0,0,0}, v1 = {0,0,0,0};
        if (ee < E_N)
            v0 = __ldcs((const float4*)(review_feat + ((size_t)r * E_N + ee) * 256 + 128) + q);
        if (ee + 1 < E_N)
            v1 = __ldcs((const float4*)(review_feat + ((size_t)r * E_N + ee + 1) * 256 + 128) + q);
        ulonglong2 za, zb;
        za.x = pack2(v0.x, v1.x);
        za.y = pack2(v0.y, v1.y);
        zb.x = pack2(v0.z, v1.z);
        zb.y = pack2(v0.w, v1.w);
        smrf[p * 33 + q * 2]     = za;
        smrf[p * 33 + q * 2 + 1] = zb;
    }

    if (tid < PS_EDGES) {
        int eg = e0 + tid;
        if (eg < E_N) {
            const size_t idx = (size_t)r * E_N + eg;
            const int row = rows[idx];
            const int col = cols[idx];
            const float ead = g_ead[idx];
            const float w = ead * rsqrtf(g_norm_u[row] * g_norm_i[col]);
            int_dist_out[idx] = w;
            smw[tid] = w;
            smrc[tid] = make_int2(row, col);
        }
    }
    __syncthreads();

    const int lane = tid & 31;
    const int warp = tid >> 5;
    const int p_local = lane >> 3;
    const int o4 = lane & 7;
    const int pair = warp * 4 + p_local;
    {
        unsigned long long acc2[4] = {0ull, 0ull, 0ull, 0ull};
        const ulonglong2* rfp = smrf + pair * 33;
        const float* wp = smW + o4 * 4;
#pragma unroll
        for (int jq = 0; jq < 16; jq++) {
            ulonglong2 rva = rfp[jq * 2];
            ulonglong2 rvb = rfp[jq * 2 + 1];
            float4 w0 = *(const float4*)(wp + (4*jq+0) * 36);
            float4 w1 = *(const float4*)(wp + (4*jq+1) * 36);
            float4 w2 = *(const float4*)(wp + (4*jq+2) * 36);
            float4 w3 = *(const float4*)(wp + (4*jq+3) * 36);
            acc2[0] = fma2(rva.x, dup2(w0.x), acc2[0]);
            acc2[1] = fma2(rva.x, dup2(w0.y), acc2[1]);
            acc2[2] = fma2(rva.x, dup2(w0.z), acc2[2]);
            acc2[3] = fma2(rva.x, dup2(w0.w), acc2[3]);
            acc2[0] = fma2(rva.y, dup2(w1.x), acc2[0]);
            acc2[1] = fma2(rva.y, dup2(w1.y), acc2[1]);
            acc2[2] = fma2(rva.y, dup2(w1.z), acc2[2]);
            acc2[3] = fma2(rva.y, dup2(w1.w), acc2[3]);
            acc2[0] = fma2(rvb.x, dup2(w2.x), acc2[0]);
            acc2[1] = fma2(rvb.x, dup2(w2.y), acc2[1]);
            acc2[2] = fma2(rvb.x, dup2(w2.z), acc2[2]);
            acc2[3] = fma2(rvb.x, dup2(w2.w), acc2[3]);
            acc2[0] = fma2(rvb.y, dup2(w3.x), acc2[0]);
            acc2[1] = fma2(rvb.y, dup2(w3.y), acc2[1]);
            acc2[2] = fma2(rvb.y, dup2(w3.z), acc2[2]);
            acc2[3] = fma2(rvb.y, dup2(w3.w), acc2[3]);
        }
        __syncthreads();

        const int el = pair * 2;
#pragma unroll
        for (int oo = 0; oo < 4; oo++) {
            float lo, hi;
            unpack2(acc2[oo], lo, hi);
            smres[el * 33 + o4 * 4 + oo] = lo;
            smres[(el + 1) * 33 + o4 * 4 + oo] = hi;
        }
    }
    __syncthreads();

#pragma unroll
    for (int it = 0; it < 2; it++) {
        int item = tid + it * 256;
        int el = item >> 3;
        int q  = item & 7;
        int eg = e0 + el;
        if (eg >= E_N) continue;
        const float w = smw[el];
        const int2 rc = smrc[el];

        float4 p4;
        float* dest;
        const float* res = smres + el * 33;
        float m0, m1, m2, m3;
        if (q < 4) {
            m0 = res[q*4+0]; m1 = res[q*4+1]; m2 = res[q*4+2]; m3 = res[q*4+3];
            p4 = *(const float4*)(g_P_u + ((size_t)r * U_N + rc.x) * 16 + q * 4);
            dest = g_ifeat + rc.y * 16 + q * 4;
        } else {
            const int qq = q - 4;
            m0 = res[16+qq*4+0]; m1 = res[16+qq*4+1]; m2 = res[16+qq*4+2]; m3 = res[16+qq*4+3];
            p4 = *(const float4*)(g_P_i + ((size_t)r * I_N + rc.y) * 16 + qq * 4);
            dest = g_ufeat + rc.x * 16 + qq * 4;
        }
        float4 mv;
        mv.x = (m0 + p4.x) * w;
        mv.y = (m1 + p4.y) * w;
        mv.z = (m2 + p4.z) * w;
        mv.w = (m3 + p4.w) * w;
        red_v4(dest, mv);
    }
}

// ---------------- kernel 3: leaky + FC (R13 version) ----------------
#define NB_U ((U_N + 63) / 64)
#define NB_I ((I_N + 63) / 64)
__global__ __launch_bounds__(256) void fc_kernel(
    const float* __restrict__ ufc_w, const float* __restrict__ ufc_b,
    const float* __restrict__ ifc_w, const float* __restrict__ ifc_b,
    float* __restrict__ out)
{
    __shared__ float smx[64 * 20];
    const int tid = threadIdx.x;
    const bool isU = (blockIdx.x < NB_U);
    const int nb = (isU ? blockIdx.x : (blockIdx.x - NB_U)) * 64;
    const int N = isU ? U_N : I_N;
    const float* feat = isU ? g_ufeat : g_ifeat;
    const float* W = isU ? ufc_w : ifc_w;
    const float* B = isU ? ufc_b : ifc_b;
    float* outp = out + (isU ? 0 : (size_t)U_N * 64);

    for (int i = tid; i < 1024; i += 256) {
        int n = i >> 4, j = i & 15;
        int ng = nb + n;
        float x = (ng < N) ? feat[ng * 16 + j] : 0.f;
        x = (x >= 0.f) ? x : 0.1f * x;
        smx[n * 20 + j] = x;
    }
    __syncthreads();

    const int o = tid & 63;
    const int g = tid >> 6;
    float wr[16];
#pragma unroll
    for (int j = 0; j < 16; j++) wr[j] = W[j * 64 + o];
    const float b = B[o];

#pragma unroll
    for (int i = 0; i < 16; i++) {
        int n = g + i * 4;
        int ng = nb + n;
        if (ng < N) {
            float acc = b;
            const float4* xr = (const float4*)(smx + n * 20);
#pragma unroll
            for (int j4 = 0; j4 < 4; j4++) {
                float4 xq = xr[j4];
                acc = fmaf(xq.x, wr[j4*4+0], acc);
                acc = fmaf(xq.y, wr[j4*4+1], acc);
                acc = fmaf(xq.z, wr[j4*4+2], acc);
                acc = fmaf(xq.w, wr[j4*4+3], acc);
            }
            outp[(size_t)ng * 64 + o] = acc;
        }
    }
}

// ---------------- launch (single stream, serial) ----------------
extern "C" void kernel_launch(void* const* d_in, const int* in_sizes, int n_in,
                              void* d_out, int out_size)
{
    const float* user_h       = (const float*)d_in[0];
    const float* item_h       = (const float*)d_in[1];
    const float* user_hsum    = (const float*)d_in[2];
    const float* item_hsum    = (const float*)d_in[3];
    const float* review_feat  = (const float*)d_in[4];
    const float* prototypes   = (const float*)d_in[5];
    const float* eta          = (const float*)d_in[6];
    const float* node_w_fwd   = (const float*)d_in[7];
    const float* node_w_rev   = (const float*)d_in[8];
    const float* review_w_fwd = (const float*)d_in[9];
    const float* review_w_rev = (const float*)d_in[10];
    const float* ufc_w        = (const float*)d_in[11];
    const float* ufc_b        = (const float*)d_in[12];
    const float* ifc_w        = (const float*)d_in[13];
    const float* ifc_b        = (const float*)d_in[14];
    const int*   rows         = (const int*)d_in[15];
    const int*   cols         = (const int*)d_in[16];
    float* out = (float*)d_out;

    dim3 pgrid((U_N + 255) / 256, R_N, 2);
    precompute_kernel<<<pgrid, 256>>>(user_h, item_h, node_w_fwd, node_w_rev);

    dim3 egrid(E_N / 8, R_N);
    phase1_kernel<<<egrid, 256>>>(user_h, item_h, user_hsum, item_hsum,
                                  review_feat, prototypes, eta, rows, cols);

    dim3 bgrid((E_N + PS_EDGES - 1) / PS_EDGES, R_N);
    proj_scatter_kernel<<<bgrid, 256>>>(review_feat, review_w_fwd, review_w_rev,
                                        rows, cols,
                                        out + (size_t)(U_N + I_N) * OUT_N);

    fc_kernel<<<NB_U + NB_I, 256>>>(ufc_w, ufc_b, ifc_w, ifc_b, out);
}

// round 17
// speedup vs baseline: 1.1286x; 1.0068x over previous
#include <cuda_runtime.h>
#include <cstdint>

#define U_N   100000
#define I_N   50000
#define R_N   5
#define E_N   100000
#define K_N   4
#define D_N   16
#define RD_N  64
#define OUT_N 64
#define KF_N  2
#define PS_EDGES 64

// ---------------- device scratch ----------------
__device__ float g_norm_u[U_N];
__device__ float g_norm_i[I_N];
__device__ float g_ead[R_N * E_N];
__device__ float g_ufeat[U_N * D_N];
__device__ float g_ifeat[I_N * D_N];
__device__ float g_P_u[(size_t)R_N * U_N * D_N];
__device__ float g_P_i[(size_t)R_N * I_N * D_N];

// ---------------- helpers ----------------
__device__ __forceinline__ float red16(float v) {
    v += __shfl_xor_sync(0xffffffffu, v, 1);
    v += __shfl_xor_sync(0xffffffffu, v, 2);
    v += __shfl_xor_sync(0xffffffffu, v, 4);
    v += __shfl_xor_sync(0xffffffffu, v, 8);
    return v;
}
__device__ __forceinline__ void red_v4(float* addr, float4 v) {
    asm volatile("red.global.add.v4.f32 [%0], {%1, %2, %3, %4};"
                 :: "l"(addr), "f"(v.x), "f"(v.y), "f"(v.z), "f"(v.w)
                 : "memory");
}
__device__ __forceinline__ unsigned long long dup2(float v) {
    unsigned long long d;
    asm("mov.b64 %0, {%1, %1};" : "=l"(d) : "f"(v));
    return d;
}
__device__ __forceinline__ unsigned long long pack2(float lo, float hi) {
    unsigned long long d;
    asm("mov.b64 %0, {%1, %2};" : "=l"(d) : "f"(lo), "f"(hi));
    return d;
}
__device__ __forceinline__ unsigned long long fma2(unsigned long long a,
                                                   unsigned long long b,
                                                   unsigned long long c) {
    unsigned long long d;
    asm("fma.rn.f32x2 %0, %1, %2, %3;" : "=l"(d) : "l"(a), "l"(b), "l"(c));
    return d;
}
__device__ __forceinline__ void unpack2(unsigned long long v, float& lo, float& hi) {
    asm("mov.b64 {%0, %1}, %2;" : "=f"(lo), "=f"(hi) : "l"(v));
}

// ---------------- kernel A: node projection + accumulator zeroing ----------------
__global__ __launch_bounds__(256) void precompute_kernel(
    const float* __restrict__ user_h, const float* __restrict__ item_h,
    const float* __restrict__ node_w_fwd, const float* __restrict__ node_w_rev)
{
    __shared__ float sw[256];
    const int r = blockIdx.y;
    const bool isU = (blockIdx.z == 0);
    const float* W = isU ? node_w_fwd : node_w_rev;
    if (threadIdx.x < 256) sw[threadIdx.x] = W[r * 256 + threadIdx.x];
    __syncthreads();

    const int N = isU ? U_N : I_N;
    const int n = blockIdx.x * 256 + threadIdx.x;
    if (n >= N) return;

    if (r == 0) {
        float4 z = {0.f, 0.f, 0.f, 0.f};
        if (isU) {
            g_norm_u[n] = 0.f;
            float4* f = (float4*)(g_ufeat + n * 16);
            f[0] = z; f[1] = z; f[2] = z; f[3] = z;
        } else {
            g_norm_i[n] = 0.f;
            float4* f = (float4*)(g_ifeat + n * 16);
            f[0] = z; f[1] = z; f[2] = z; f[3] = z;
        }
    }

    const float* h = (isU ? user_h : item_h) + ((size_t)r * N + n) * 16;
    float xs[16];
    const float4* h4 = (const float4*)h;
    float4 x0 = h4[0], x1 = h4[1], x2 = h4[2], x3 = h4[3];
    xs[0]=x0.x; xs[1]=x0.y; xs[2]=x0.z; xs[3]=x0.w;
    xs[4]=x1.x; xs[5]=x1.y; xs[6]=x1.z; xs[7]=x1.w;
    xs[8]=x2.x; xs[9]=x2.y; xs[10]=x2.z; xs[11]=x2.w;
    xs[12]=x3.x; xs[13]=x3.y; xs[14]=x3.z; xs[15]=x3.w;

    float4 a0 = {0,0,0,0}, a1 = {0,0,0,0}, a2 = {0,0,0,0}, a3 = {0,0,0,0};
    const float4* sw4 = (const float4*)sw;
#pragma unroll
    for (int j = 0; j < 16; j++) {
        float xv = xs[j];
        float4 w0 = sw4[j*4+0], w1 = sw4[j*4+1], w2 = sw4[j*4+2], w3 = sw4[j*4+3];
        a0.x = fmaf(xv, w0.x, a0.x); a0.y = fmaf(xv, w0.y, a0.y);
        a0.z = fmaf(xv, w0.z, a0.z); a0.w = fmaf(xv, w0.w, a0.w);
        a1.x = fmaf(xv, w1.x, a1.x); a1.y = fmaf(xv, w1.y, a1.y);
        a1.z = fmaf(xv, w1.z, a1.z); a1.w = fmaf(xv, w1.w, a1.w);
        a2.x = fmaf(xv, w2.x, a2.x); a2.y = fmaf(xv, w2.y, a2.y);
        a2.z = fmaf(xv, w2.z, a2.z); a2.w = fmaf(xv, w2.w, a2.w);
        a3.x = fmaf(xv, w3.x, a3.x); a3.y = fmaf(xv, w3.y, a3.y);
        a3.z = fmaf(xv, w3.z, a3.z); a3.w = fmaf(xv, w3.w, a3.w);
    }
    float4* P = (float4*)((isU ? g_P_u : g_P_i) + ((size_t)r * N + n) * 16);
    P[0] = a0; P[1] = a1; P[2] = a2; P[3] = a3;
}

// ---------------- kernel 1: per-edge ead (R13/R16 measured-best version) ----------------
__global__ __launch_bounds__(256) void phase1_kernel(
    const float* __restrict__ user_h,     const float* __restrict__ item_h,
    const float* __restrict__ user_hsum,  const float* __restrict__ item_hsum,
    const float* __restrict__ review_feat,
    const float* __restrict__ prototypes, const float* __restrict__ eta,
    const int*   __restrict__ rows,       const int*   __restrict__ cols)
{
    __shared__ float sm[256];
    const int r = blockIdx.y;
    if (threadIdx.x < 256) sm[threadIdx.x] = prototypes[threadIdx.x];
    __syncthreads();

    const int lane = threadIdx.x & 31;
    const int warp = threadIdx.x >> 5;
    const int e = blockIdx.x * 8 + warp;
    if (e >= E_N) return;

    const size_t idx = (size_t)r * E_N + e;
    const int row = rows[idx];
    const int col = cols[idx];
    const unsigned FULL = 0xffffffffu;

    const int dh = lane & 15;
    float hval;
    if (lane < 16) hval = __ldg(user_h + ((size_t)r * U_N + row) * 16 + dh);
    else           hval = __ldg(item_h + ((size_t)r * I_N + col) * 16 + dh);

    const float* uh = user_hsum + ((size_t)r * U_N + row) * 64;
    const float* ih = item_hsum + ((size_t)r * I_N + col) * 64;
    float4 hs;
    if (lane < 16) hs = *(const float4*)(uh + 4 * lane);
    else           hs = *(const float4*)(ih + 4 * (lane - 16));

    const float4* rf4 = (const float4*)(review_feat + idx * 256);
    float4 ra = __ldcs(rf4 + lane * 2);
    float4 rb = __ldcs(rf4 + lane * 2 + 1);

    const float etav = eta[idx];

    float othv = __shfl_xor_sync(FULL, hval, 16);
    float dot = red16(hval * othv);
    float ss = red16(hval * hval);
    float oss = __shfl_xor_sync(FULL, ss, 16);
    float sim_k = 2.0f * dot * rsqrtf(ss * oss);

    float4 o4;
    o4.x = __shfl_xor_sync(FULL, hs.x, 16);
    o4.y = __shfl_xor_sync(FULL, hs.y, 16);
    o4.z = __shfl_xor_sync(FULL, hs.z, 16);
    o4.w = __shfl_xor_sync(FULL, hs.w, 16);
    float p = hs.x * o4.x + hs.y * o4.y + hs.z * o4.z + hs.w * o4.w;
    p += __shfl_xor_sync(FULL, p, 1);
    p += __shfl_xor_sync(FULL, p, 2);
    float ek = __expf(2.0f * p);
    float Ssim = ek;
    Ssim += __shfl_xor_sync(FULL, Ssim, 4);
    Ssim += __shfl_xor_sync(FULL, Ssim, 8);
    float exp_sim = __expf(sim_k) / Ssim;

    const float4* pr4 = (const float4*)sm;
    float4 pa = pr4[lane * 2];
    float4 pb = pr4[lane * 2 + 1];
    float ad = ra.x * pa.x + ra.y * pa.y + ra.z * pa.z + ra.w * pa.w
             + rb.x * pb.x + rb.y * pb.y + rb.z * pb.z + rb.w * pb.w;
    ad += __shfl_xor_sync(FULL, ad, 1);
    ad += __shfl_xor_sync(FULL, ad, 2);
    ad += __shfl_xor_sync(FULL, ad, 4);
    float eab = __expf(2.0f * ad);
    float Sad = eab;
    Sad += __shfl_xor_sync(FULL, Sad, 8);
    Sad += __shfl_xor_sync(FULL, Sad, 16);
    float e2 = __shfl_sync(FULL, eab, 16);
    float ead = e2 / Sad;

    float g = 1.0f / (1.0f + __expf(-etav));
    ead = g * ead + (1.0f - g) * exp_sim;

    if (lane == 0) {
        g_ead[idx] = ead;
        atomicAdd(&g_norm_u[row], ead);
        atomicAdd(&g_norm_i[col], ead);
    }
}

// ---------------- fused kernel: zip-staging GEMM + w-stage + scatter (R13/R16) ----------------
__global__ __launch_bounds__(256) void proj_scatter_kernel(
    const float* __restrict__ review_feat,
    const float* __restrict__ review_w_fwd, const float* __restrict__ review_w_rev,
    const int* __restrict__ rows, const int* __restrict__ cols,
    float* __restrict__ int_dist_out)
{
    __shared__ float      smW[64 * 36];
    __shared__ ulonglong2 smrf[32 * 33];
    __shared__ float      smw[PS_EDGES];
    __shared__ int2       smrc[PS_EDGES];
    float* smres = (float*)smrf;                    // overlay after GEMM

    const int r = blockIdx.y;
    const int tid = threadIdx.x;
    const int e0 = blockIdx.x * PS_EDGES;

    for (int i = tid; i < 2048; i += 256) {
        int o = i & 31, j = i >> 5;
        float w = (o < 16) ? review_w_fwd[r * 1024 + j * 16 + o]
                           : review_w_rev[r * 1024 + j * 16 + (o - 16)];
        smW[j * 36 + o] = w;
    }

    for (int i = tid; i < 512; i += 256) {
        int p = i >> 4, q = i & 15;
        int ee = e0 + 2 * p;
        float4 v0 = {0,0,0,0}, v1 = {0,0,0,0};
        if (ee < E_N)
            v0 = __ldcs((const float4*)(review_feat + ((size_t)r * E_N + ee) * 256 + 128) + q);
        if (ee + 1 < E_N)
            v1 = __ldcs((const float4*)(review_feat + ((size_t)r * E_N + ee + 1) * 256 + 128) + q);
        ulonglong2 za, zb;
        za.x = pack2(v0.x, v1.x);
        za.y = pack2(v0.y, v1.y);
        zb.x = pack2(v0.z, v1.z);
        zb.y = pack2(v0.w, v1.w);
        smrf[p * 33 + q * 2]     = za;
        smrf[p * 33 + q * 2 + 1] = zb;
    }

    if (tid < PS_EDGES) {
        int eg = e0 + tid;
        if (eg < E_N) {
            const size_t idx = (size_t)r * E_N + eg;
            const int row = rows[idx];
            const int col = cols[idx];
            const float ead = g_ead[idx];
            const float w = ead * rsqrtf(g_norm_u[row] * g_norm_i[col]);
            int_dist_out[idx] = w;
            smw[tid] = w;
            smrc[tid] = make_int2(row, col);
        }
    }
    __syncthreads();

    const int lane = tid & 31;
    const int warp = tid >> 5;
    const int p_local = lane >> 3;
    const int o4 = lane & 7;
    const int pair = warp * 4 + p_local;
    {
        unsigned long long acc2[4] = {0ull, 0ull, 0ull, 0ull};
        const ulonglong2* rfp = smrf + pair * 33;
        const float* wp = smW + o4 * 4;
#pragma unroll
        for (int jq = 0; jq < 16; jq++) {
            ulonglong2 rva = rfp[jq * 2];
            ulonglong2 rvb = rfp[jq * 2 + 1];
            float4 w0 = *(const float4*)(wp + (4*jq+0) * 36);
            float4 w1 = *(const float4*)(wp + (4*jq+1) * 36);
            float4 w2 = *(const float4*)(wp + (4*jq+2) * 36);
            float4 w3 = *(const float4*)(wp + (4*jq+3) * 36);
            acc2[0] = fma2(rva.x, dup2(w0.x), acc2[0]);
            acc2[1] = fma2(rva.x, dup2(w0.y), acc2[1]);
            acc2[2] = fma2(rva.x, dup2(w0.z), acc2[2]);
            acc2[3] = fma2(rva.x, dup2(w0.w), acc2[3]);
            acc2[0] = fma2(rva.y, dup2(w1.x), acc2[0]);
            acc2[1] = fma2(rva.y, dup2(w1.y), acc2[1]);
            acc2[2] = fma2(rva.y, dup2(w1.z), acc2[2]);
            acc2[3] = fma2(rva.y, dup2(w1.w), acc2[3]);
            acc2[0] = fma2(rvb.x, dup2(w2.x), acc2[0]);
            acc2[1] = fma2(rvb.x, dup2(w2.y), acc2[1]);
            acc2[2] = fma2(rvb.x, dup2(w2.z), acc2[2]);
            acc2[3] = fma2(rvb.x, dup2(w2.w), acc2[3]);
            acc2[0] = fma2(rvb.y, dup2(w3.x), acc2[0]);
            acc2[1] = fma2(rvb.y, dup2(w3.y), acc2[1]);
            acc2[2] = fma2(rvb.y, dup2(w3.z), acc2[2]);
            acc2[3] = fma2(rvb.y, dup2(w3.w), acc2[3]);
        }
        __syncthreads();

        const int el = pair * 2;
#pragma unroll
        for (int oo = 0; oo < 4; oo++) {
            float lo, hi;
            unpack2(acc2[oo], lo, hi);
            smres[el * 33 + o4 * 4 + oo] = lo;
            smres[(el + 1) * 33 + o4 * 4 + oo] = hi;
        }
    }
    __syncthreads();

#pragma unroll
    for (int it = 0; it < 2; it++) {
        int item = tid + it * 256;
        int el = item >> 3;
        int q  = item & 7;
        int eg = e0 + el;
        if (eg >= E_N) continue;
        const float w = smw[el];
        const int2 rc = smrc[el];

        float4 p4;
        float* dest;
        const float* res = smres + el * 33;
        float m0, m1, m2, m3;
        if (q < 4) {
            m0 = res[q*4+0]; m1 = res[q*4+1]; m2 = res[q*4+2]; m3 = res[q*4+3];
            p4 = *(const float4*)(g_P_u + ((size_t)r * U_N + rc.x) * 16 + q * 4);
            dest = g_ifeat + rc.y * 16 + q * 4;
        } else {
            const int qq = q - 4;
            m0 = res[16+qq*4+0]; m1 = res[16+qq*4+1]; m2 = res[16+qq*4+2]; m3 = res[16+qq*4+3];
            p4 = *(const float4*)(g_P_i + ((size_t)r * I_N + rc.y) * 16 + qq * 4);
            dest = g_ufeat + rc.x * 16 + qq * 4;
        }
        float4 mv;
        mv.x = (m0 + p4.x) * w;
        mv.y = (m1 + p4.y) * w;
        mv.z = (m2 + p4.z) * w;
        mv.w = (m3 + p4.w) * w;
        red_v4(dest, mv);
    }
}

// ---------------- kernel 3: leaky + FC, node-pair FFMA2 ----------------
// Block = 64 nodes = 32 pairs. smxz[pair][jq] : ulonglong2 = {pack2(x0[2jq],x1[2jq]),
// pack2(x0[2jq+1],x1[2jq+1])}, row stride 9 units. Thread: o = tid&63, g = tid>>6,
// handles 8 pairs (g*8 .. g*8+7).
#define NB_U ((U_N + 63) / 64)
#define NB_I ((I_N + 63) / 64)
__global__ __launch_bounds__(256) void fc_kernel(
    const float* __restrict__ ufc_w, const float* __restrict__ ufc_b,
    const float* __restrict__ ifc_w, const float* __restrict__ ifc_b,
    float* __restrict__ out)
{
    __shared__ ulonglong2 smxz[32 * 9];
    const int tid = threadIdx.x;
    const bool isU = (blockIdx.x < NB_U);
    const int nb = (isU ? blockIdx.x : (blockIdx.x - NB_U)) * 64;
    const int N = isU ? U_N : I_N;
    const float* feat = isU ? g_ufeat : g_ifeat;
    const float* W = isU ? ufc_w : ifc_w;
    const float* B = isU ? ufc_b : ifc_b;
    float* outp = out + (isU ? 0 : (size_t)U_N * 64);

    // stage: 32 pairs x 4 float4-chunks = 128 tasks
    for (int i = tid; i < 128; i += 256) {
        int p = i >> 2, q = i & 3;
        int n0 = nb + 2 * p, n1 = n0 + 1;
        float4 v0 = {0,0,0,0}, v1 = {0,0,0,0};
        if (n0 < N) v0 = *((const float4*)(feat + n0 * 16) + q);
        if (n1 < N) v1 = *((const float4*)(feat + n1 * 16) + q);
        v0.x = (v0.x >= 0.f) ? v0.x : 0.1f * v0.x;
        v0.y = (v0.y >= 0.f) ? v0.y : 0.1f * v0.y;
        v0.z = (v0.z >= 0.f) ? v0.z : 0.1f * v0.z;
        v0.w = (v0.w >= 0.f) ? v0.w : 0.1f * v0.w;
        v1.x = (v1.x >= 0.f) ? v1.x : 0.1f * v1.x;
        v1.y = (v1.y >= 0.f) ? v1.y : 0.1f * v1.y;
        v1.z = (v1.z >= 0.f) ? v1.z : 0.1f * v1.z;
        v1.w = (v1.w >= 0.f) ? v1.w : 0.1f * v1.w;
        ulonglong2 za, zb;
        za.x = pack2(v0.x, v1.x);   // j = 4q
        za.y = pack2(v0.y, v1.y);   // j = 4q+1
        zb.x = pack2(v0.z, v1.z);   // j = 4q+2
        zb.y = pack2(v0.w, v1.w);   // j = 4q+3
        smxz[p * 9 + q * 2]     = za;
        smxz[p * 9 + q * 2 + 1] = zb;
    }
    __syncthreads();

    const int o = tid & 63;
    const int g = tid >> 6;
    float wr[16];
#pragma unroll
    for (int j = 0; j < 16; j++) wr[j] = W[j * 64 + o];
    const float b = B[o];
    const unsigned long long b2 = pack2(b, b);

#pragma unroll
    for (int i = 0; i < 8; i++) {
        int p = g * 8 + i;
        int n0 = nb + 2 * p;
        if (n0 >= N) break;
        unsigned long long acc2 = b2;
        const ulonglong2* xz = smxz + p * 9;
#pragma unroll
        for (int jq = 0; jq < 4; jq++) {
            ulonglong2 za = xz[jq * 2];
            ulonglong2 zb = xz[jq * 2 + 1];
            acc2 = fma2(za.x, dup2(wr[4*jq+0]), acc2);
            acc2 = fma2(za.y, dup2(wr[4*jq+1]), acc2);
            acc2 = fma2(zb.x, dup2(wr[4*jq+2]), acc2);
            acc2 = fma2(zb.y, dup2(wr[4*jq+3]), acc2);
        }
        float lo, hi;
        unpack2(acc2, lo, hi);
        outp[(size_t)n0 * 64 + o] = lo;
        if (n0 + 1 < N) outp[(size_t)(n0 + 1) * 64 + o] = hi;
    }
}

// ---------------- launch (single stream, serial) ----------------
extern "C" void kernel_launch(void* const* d_in, const int* in_sizes, int n_in,
                              void* d_out, int out_size)
{
    const float* user_h       = (const float*)d_in[0];
    const float* item_h       = (const float*)d_in[1];
    const float* user_hsum    = (const float*)d_in[2];
    const float* item_hsum    = (const float*)d_in[3];
    const float* review_feat  = (const float*)d_in[4];
    const float* prototypes   = (const float*)d_in[5];
    const float* eta          = (const float*)d_in[6];
    const float* node_w_fwd   = (const float*)d_in[7];
    const float* node_w_rev   = (const float*)d_in[8];
    const float* review_w_fwd = (const float*)d_in[9];
    const float* review_w_rev = (const float*)d_in[10];
    const float* ufc_w        = (const float*)d_in[11];
    const float* ufc_b        = (const float*)d_in[12];
    const float* ifc_w        = (const float*)d_in[13];
    const float* ifc_b        = (const float*)d_in[14];
    const int*   rows         = (const int*)d_in[15];
    const int*   cols         = (const int*)d_in[16];
    float* out = (float*)d_out;

    dim3 pgrid((U_N + 255) / 256, R_N, 2);
    precompute_kernel<<<pgrid, 256>>>(user_h, item_h, node_w_fwd, node_w_rev);

    dim3 egrid(E_N / 8, R_N);
    phase1_kernel<<<egrid, 256>>>(user_h, item_h, user_hsum, item_hsum,
                                  review_feat, prototypes, eta, rows, cols);

    dim3 bgrid((E_N + PS_EDGES - 1) / PS_EDGES, R_N);
    proj_scatter_kernel<<<bgrid, 256>>>(review_feat, review_w_fwd, review_w_rev,
                                        rows, cols,
                                        out + (size_t)(U_N + I_N) * OUT_N);

    fc_kernel<<<NB_U + NB_I, 256>>>(ufc_w, ufc_b, ifc_w, ifc_b, out);
}